// round 2
// baseline (speedup 1.0000x reference)
#include <cuda_runtime.h>
#include <cstdint>

// Shapes: L=16, N=128, C=10, D=13, H=128, HID=64, F=88
#define DINL __device__ __forceinline__

// ------------------------- device scratch -------------------------
__device__ __align__(16) float g_h1[4096 * 128];   // LSTM1 final hidden
__device__ __align__(16) float g_lo[2048 * 64];    // lo pre-BN
__device__ float g_sc1[64], g_sh1[64];             // BN1 scale/shift
__device__ __align__(16) float g_Wcat[256 * 640];  // [Wlh|Wrh] repacked
__device__ float g_base[15 * 128];                 // per-step base vectors (a=0)
__device__ __align__(16) float g_h[2][128 * 128];  // tree h state (ping-pong)
__device__ __align__(16) float g_c[2][128 * 128];  // tree c state (ping-pong)
__device__ __align__(16) float g_P[128 * 640];     // tree projection per step
__device__ float g_sc2[128], g_sh2[128];           // BN2
__device__ __align__(16) float g_t1[128 * 64];
__device__ float g_sc3[64], g_sh3[64];             // BN3

// ------------------------- helpers -------------------------
DINL float sigf(float x) { return __fdividef(1.f, 1.f + __expf(-x)); }
DINL float tanh_(float x) { return 2.f * sigf(2.f * x) - 1.f; }
DINL void fma2(unsigned long long& a, unsigned long long b, unsigned long long c) {
    asm("fma.rn.f32x2 %0, %1, %2, %0;" : "+l"(a) : "l"(b), "l"(c));
}
DINL unsigned long long dup2(float x) {
    unsigned long long r;
    asm("mov.b64 %0, {%1, %1};" : "=l"(r) : "f"(x));
    return r;
}
DINL float2 unp2(unsigned long long v) {
    float2 f;
    asm("mov.b64 {%0, %1}, %2;" : "=f"(f.x), "=f"(f.y) : "l"(v));
    return f;
}

// ---------------------------------------------------------------------------
// K1: LSTM1 over c_all = concat(cond1, cond2) : 4096 rows x 10 steps, D=13->H=128
// Block = 256 threads = 8 warps; each warp owns 4 rows for the full sequence.
// z row layout: [0..127] = h, [128..140] = x_t. Gate cols: i,f,g,o = j*128.
// Lane owns hidden cols lane*4..lane*4+3 per gate (2 f32x2 pairs).
// ---------------------------------------------------------------------------
__global__ void __launch_bounds__(256) lstm1_kernel(
    const float* __restrict__ cond1, const float* __restrict__ cond2,
    const float* __restrict__ Wih, const float* __restrict__ Whh,
    const float* __restrict__ bias)
{
    __shared__ float z[32][144];
    const int tid = threadIdx.x, warp = tid >> 5, lane = tid & 31;
    const int lr0 = warp * 4;
    const int row0 = blockIdx.x * 32 + lr0;

    float4 zero4 = make_float4(0.f, 0.f, 0.f, 0.f);
#pragma unroll
    for (int r = 0; r < 4; r++) *(float4*)&z[lr0 + r][lane * 4] = zero4;

    float cst[4][4] = {};
    const float* src[4];
#pragma unroll
    for (int r = 0; r < 4; r++) {
        int gr = row0 + r;
        src[r] = (gr < 2048) ? (cond1 + (size_t)gr * 130)
                             : (cond2 + (size_t)(gr - 2048) * 130);
    }
    __syncwarp();

    const ulonglong2* Wh2 = (const ulonglong2*)Whh;  // row k = 128 ulonglong2
    const ulonglong2* Wi2 = (const ulonglong2*)Wih;

    for (int t = 0; t < 10; t++) {
        // load x_t for this warp's 4 rows (4*13 = 52 floats)
        for (int idx = lane; idx < 52; idx += 32) {
            int r = idx / 13, c = idx - r * 13;
            z[lr0 + r][128 + c] = src[r][t * 13 + c];
        }
        __syncwarp();

        unsigned long long acc[4][8];
#pragma unroll
        for (int j = 0; j < 4; j++) {
            ulonglong2 bb = *(const ulonglong2*)(bias + j * 128 + lane * 4);
#pragma unroll
            for (int r = 0; r < 4; r++) { acc[r][2 * j] = bb.x; acc[r][2 * j + 1] = bb.y; }
        }

        // h @ Whh
#pragma unroll 2
        for (int k = 0; k < 128; k++) {
            ulonglong2 w0 = Wh2[k * 128 + 0 * 32 + lane];
            ulonglong2 w1 = Wh2[k * 128 + 1 * 32 + lane];
            ulonglong2 w2 = Wh2[k * 128 + 2 * 32 + lane];
            ulonglong2 w3 = Wh2[k * 128 + 3 * 32 + lane];
#pragma unroll
            for (int r = 0; r < 4; r++) {
                unsigned long long a = dup2(z[lr0 + r][k]);
                fma2(acc[r][0], a, w0.x); fma2(acc[r][1], a, w0.y);
                fma2(acc[r][2], a, w1.x); fma2(acc[r][3], a, w1.y);
                fma2(acc[r][4], a, w2.x); fma2(acc[r][5], a, w2.y);
                fma2(acc[r][6], a, w3.x); fma2(acc[r][7], a, w3.y);
            }
        }
        // x @ Wih
#pragma unroll
        for (int k = 0; k < 13; k++) {
            ulonglong2 w0 = Wi2[k * 128 + 0 * 32 + lane];
            ulonglong2 w1 = Wi2[k * 128 + 1 * 32 + lane];
            ulonglong2 w2 = Wi2[k * 128 + 2 * 32 + lane];
            ulonglong2 w3 = Wi2[k * 128 + 3 * 32 + lane];
#pragma unroll
            for (int r = 0; r < 4; r++) {
                unsigned long long a = dup2(z[lr0 + r][128 + k]);
                fma2(acc[r][0], a, w0.x); fma2(acc[r][1], a, w0.y);
                fma2(acc[r][2], a, w1.x); fma2(acc[r][3], a, w1.y);
                fma2(acc[r][4], a, w2.x); fma2(acc[r][5], a, w2.y);
                fma2(acc[r][6], a, w3.x); fma2(acc[r][7], a, w3.y);
            }
        }
        __syncwarp();

#pragma unroll
        for (int r = 0; r < 4; r++) {
            float2 i01 = unp2(acc[r][0]), i23 = unp2(acc[r][1]);
            float2 f01 = unp2(acc[r][2]), f23 = unp2(acc[r][3]);
            float2 G01 = unp2(acc[r][4]), G23 = unp2(acc[r][5]);
            float2 o01 = unp2(acc[r][6]), o23 = unp2(acc[r][7]);
            float iv[4] = {i01.x, i01.y, i23.x, i23.y};
            float fv[4] = {f01.x, f01.y, f23.x, f23.y};
            float gv[4] = {G01.x, G01.y, G23.x, G23.y};
            float ov[4] = {o01.x, o01.y, o23.x, o23.y};
            float hv[4];
#pragma unroll
            for (int q = 0; q < 4; q++) {
                float c = sigf(fv[q]) * cst[r][q] + sigf(iv[q]) * tanh_(gv[q]);
                cst[r][q] = c;
                hv[q] = sigf(ov[q]) * tanh_(c);
            }
            *(float4*)&z[lr0 + r][lane * 4] = make_float4(hv[0], hv[1], hv[2], hv[3]);
        }
        __syncwarp();
    }

#pragma unroll
    for (int r = 0; r < 4; r++)
        *(float4*)&g_h1[(size_t)(row0 + r) * 128 + lane * 4] =
            *(float4*)&z[lr0 + r][lane * 4];
}

// ---------------------------------------------------------------------------
// K2: lo = 0.5*(relu(h1@Wc+bc)+relu(h2@Wc+bc))  (2048x64), 16 rows/block
// ---------------------------------------------------------------------------
__global__ void __launch_bounds__(256) lo_kernel(const float* __restrict__ Wc,
                                                 const float* __restrict__ bc)
{
    __shared__ float ha[16][128], hb[16][128];
    int tid = threadIdx.x, r0 = blockIdx.x * 16;
    for (int i = tid; i < 16 * 128; i += 256) {
        int r = i >> 7, h = i & 127;
        ha[r][h] = g_h1[(size_t)(r0 + r) * 128 + h];
        hb[r][h] = g_h1[(size_t)(2048 + r0 + r) * 128 + h];
    }
    __syncthreads();
    for (int o = tid; o < 16 * 64; o += 256) {
        int r = o >> 6, j = o & 63;
        float s1 = bc[j], s2 = s1;
        for (int h = 0; h < 128; h++) {
            float w = Wc[h * 64 + j];
            s1 += ha[r][h] * w;
            s2 += hb[r][h] * w;
        }
        g_lo[(size_t)(r0 + r) * 64 + j] = 0.5f * (fmaxf(s1, 0.f) + fmaxf(s2, 0.f));
    }
}

// ---------------------------------------------------------------------------
// K3: batch-norm stats -> scale/shift.  which: 0=lo(2048x64), 1=hfin(128x128),
// 2=t1(128x64).  One block, 256 threads.
// ---------------------------------------------------------------------------
__global__ void __launch_bounds__(256) bn_stats_kernel(int which,
                                                       const float* __restrict__ g,
                                                       const float* __restrict__ be)
{
    const float* src; float* scale; float* shift; int R, C;
    if (which == 0)      { src = g_lo;   scale = g_sc1; shift = g_sh1; R = 2048; C = 64; }
    else if (which == 1) { src = g_h[1]; scale = g_sc2; shift = g_sh2; R = 128;  C = 128; }
    else                 { src = g_t1;   scale = g_sc3; shift = g_sh3; R = 128;  C = 64; }

    int tid = threadIdx.x;
    int parts = 256 / C;
    int col = tid % C, part = tid / C;
    float s = 0.f, s2 = 0.f;
    for (int r = part; r < R; r += parts) {
        float v = src[(size_t)r * C + col];
        s += v; s2 += v * v;
    }
    __shared__ float sh[256], sh2[256];
    sh[tid] = s; sh2[tid] = s2;
    __syncthreads();
    if (part == 0) {
        for (int p = 1; p < parts; p++) { s += sh[p * C + col]; s2 += sh2[p * C + col]; }
        float m = s / (float)R;
        float v = s2 / (float)R - m * m;
        float sc = g[col] * rsqrtf(v + 1e-5f);
        scale[col] = sc;
        shift[col] = be[col] - m * sc;
    }
}

// ---------------------------------------------------------------------------
// K4: repack Wcat[h, g*128+k] = h<128 ? Wlh[g,h,k] : Wrh[g,h-128,k]
// ---------------------------------------------------------------------------
__global__ void __launch_bounds__(1024) wcat_kernel(const float* __restrict__ Wlh,
                                                    const float* __restrict__ Wrh)
{
    int i = blockIdx.x * 1024 + threadIdx.x;
    if (i >= 256 * 640) return;
    int h = i / 640, col = i - h * 640;
    int g = col >> 7, k = col & 127;
    g_Wcat[i] = (h < 128) ? Wlh[g * 16384 + h * 128 + k]
                          : Wrh[g * 16384 + (h - 128) * 128 + k];
}

// ---------------------------------------------------------------------------
// K5: LSTM2 single step from zero state (h@Whh2 term vanishes).
// gates = x(88)@Wih2 + b2, per row n of out[15].  grid(128), block(128).
// ---------------------------------------------------------------------------
__global__ void __launch_bounds__(128) lstm2_kernel(
    const float* __restrict__ ops, const float* __restrict__ ext,
    const float* __restrict__ card, const float* __restrict__ Wih2,
    const float* __restrict__ b2)
{
    __shared__ float x[88];
    int n = blockIdx.x, k = threadIdx.x;
    if (k < 15)      x[k] = ops[(15 * 128 + n) * 15 + k];
    else if (k < 22) x[k] = ext[(15 * 128 + n) * 7 + (k - 15)];
    else if (k < 24) x[k] = card[(15 * 128 + n) * 2 + (k - 22)];
    else if (k < 88) x[k] = g_lo[(size_t)(15 * 128 + n) * 64 + (k - 24)] * g_sc1[k - 24] + g_sh1[k - 24];
    __syncthreads();

    float gi = b2[k], gg = b2[256 + k], go = b2[384 + k];
    for (int j = 0; j < 88; j++) {
        float xv = x[j];
        const float* w = Wih2 + j * 512;
        gi += xv * w[k];
        gg += xv * w[256 + k];
        go += xv * w[384 + k];
    }
    float c = sigf(gi) * tanh_(gg);       // sig(f)*c_prev = 0
    float h = sigf(go) * tanh_(c);
    g_h[0][n * 128 + k] = h;
    g_c[0][n * 128 + k] = c;
}

// ---------------------------------------------------------------------------
// K6: base_s = out[14-s][row 0] @ Win + bin_.  Block l handles level l.
// ---------------------------------------------------------------------------
__global__ void __launch_bounds__(128) base_kernel(
    const float* __restrict__ ops, const float* __restrict__ ext,
    const float* __restrict__ card, const float* __restrict__ Win,
    const float* __restrict__ bin_)
{
    __shared__ float x[88];
    int l = blockIdx.x, k = threadIdx.x;
    if (k < 15)      x[k] = ops[(l * 128 + 0) * 15 + k];
    else if (k < 22) x[k] = ext[(l * 128 + 0) * 7 + (k - 15)];
    else if (k < 24) x[k] = card[(l * 128 + 0) * 2 + (k - 22)];
    else if (k < 88) x[k] = g_lo[(size_t)(l * 128 + 0) * 64 + (k - 24)] * g_sc1[k - 24] + g_sh1[k - 24];
    __syncthreads();

    float s = bin_[k];
    for (int j = 0; j < 88; j++) s += x[j] * Win[j * 128 + k];
    g_base[(14 - l) * 128 + k] = s;
}

// ---------------------------------------------------------------------------
// K7: tree step GEMM: P = [lh|rh](128x256) @ Wcat(256x640), with gather of
// lh/rh from prev state via mapping. grid(8,5), block 128.
// Thread computes 2 rows x 8 cols using f32x2 FMAs.
// ---------------------------------------------------------------------------
__global__ void __launch_bounds__(128) tree_gemm_kernel(const int* __restrict__ mapping,
                                                        int s)
{
    int lvl = 14 - s;
    const float* __restrict__ hprev = g_h[s & 1];
    __shared__ float A[16][257];
    int tid = threadIdx.x, bx = blockIdx.x, g = blockIdx.y;

    for (int i = tid; i < 16 * 256; i += 128) {
        int r = i >> 8, h = i & 255;
        int n = bx * 16 + r;
        int mp = mapping[(lvl * 128 + n) * 2 + (h >> 7)];
        A[r][h] = (mp > 0) ? hprev[(mp - 1) * 128 + (h & 127)] : 0.f;
    }
    __syncthreads();

    int trp = tid >> 4, tc = tid & 15;
    int r0 = trp * 2;
    unsigned long long a00 = 0, a01 = 0, a02 = 0, a03 = 0;
    unsigned long long a10 = 0, a11 = 0, a12 = 0, a13 = 0;
    const float* W = g_Wcat + g * 128 + tc * 8;

#pragma unroll 4
    for (int k = 0; k < 256; k++) {
        unsigned long long v0 = dup2(A[r0][k]);
        unsigned long long v1 = dup2(A[r0 + 1][k]);
        const ulonglong2* wp = (const ulonglong2*)(W + (size_t)k * 640);
        ulonglong2 w0 = wp[0], w1 = wp[1];
        fma2(a00, v0, w0.x); fma2(a01, v0, w0.y); fma2(a02, v0, w1.x); fma2(a03, v0, w1.y);
        fma2(a10, v1, w0.x); fma2(a11, v1, w0.y); fma2(a12, v1, w1.x); fma2(a13, v1, w1.y);
    }

    int n0 = bx * 16 + r0;
    ulonglong2* P0 = (ulonglong2*)(g_P + (size_t)n0 * 640 + g * 128 + tc * 8);
    ulonglong2* P1 = (ulonglong2*)(g_P + (size_t)(n0 + 1) * 640 + g * 128 + tc * 8);
    P0[0] = make_ulonglong2(a00, a01); P0[1] = make_ulonglong2(a02, a03);
    P1[0] = make_ulonglong2(a10, a11); P1[1] = make_ulonglong2(a12, a13);
}

// ---------------------------------------------------------------------------
// K8: tree step pointwise cell update. grid(128), block(128).
// ---------------------------------------------------------------------------
__global__ void __launch_bounds__(128) tree_pw_kernel(const int* __restrict__ mapping,
                                                      const float* __restrict__ blh,
                                                      const float* __restrict__ brh,
                                                      int s)
{
    int lvl = 14 - s, p = s & 1;
    int n = blockIdx.x, k = threadIdx.x;
    int mp0 = mapping[(lvl * 128 + n) * 2 + 0];
    int mp1 = mapping[(lvl * 128 + n) * 2 + 1];
    float lc = (mp0 > 0) ? g_c[p][(mp0 - 1) * 128 + k] : 0.f;
    float rc = (mp1 > 0) ? g_c[p][(mp1 - 1) * 128 + k] : 0.f;
    float b = g_base[s * 128 + k];
    const float* P = g_P + (size_t)n * 640;

    float pre[5];
#pragma unroll
    for (int g = 0; g < 5; g++)
        pre[g] = b + P[g * 128 + k] + blh[g * 128 + k] + brh[g * 128 + k];

    float i = sigf(pre[0]), lf = sigf(pre[1]), rf = sigf(pre[2]);
    float u = tanh_(pre[3]), o = sigf(pre[4]);
    float c = i * u + lf * lc + rf * rc;
    g_c[1 - p][n * 128 + k] = c;
    g_h[1 - p][n * 128 + k] = o * tanh_(c);
}

// ---------------------------------------------------------------------------
// K9: t1 = relu(bn2(hfin) @ Wt1 + bt1)  (128x64). grid(128), block(64).
// ---------------------------------------------------------------------------
__global__ void __launch_bounds__(64) t1_kernel(const float* __restrict__ Wt1,
                                                const float* __restrict__ bt1)
{
    __shared__ float hn[128];
    int n = blockIdx.x, j = threadIdx.x;
    for (int h = j; h < 128; h += 64)
        hn[h] = g_h[1][n * 128 + h] * g_sc2[h] + g_sh2[h];
    __syncthreads();
    float s = bt1[j];
    for (int h = 0; h < 128; h++) s += hn[h] * Wt1[h * 64 + j];
    g_t1[n * 64 + j] = fmaxf(s, 0.f);
}

// ---------------------------------------------------------------------------
// K10: final: t2 = relu(bn3(t1)@Wt2+bt2); out = sigmoid(t2@Wo+bo). 1 block.
// ---------------------------------------------------------------------------
__global__ void __launch_bounds__(128) final_kernel(const float* __restrict__ Wt2,
                                                    const float* __restrict__ bt2,
                                                    const float* __restrict__ Wo,
                                                    const float* __restrict__ bo,
                                                    float* __restrict__ out)
{
    __shared__ float W2[64 * 64];
    __shared__ float wo[64];
    int tid = threadIdx.x;
    for (int i = tid; i < 4096; i += 128) W2[i] = Wt2[i];
    if (tid < 64) wo[tid] = Wo[tid];
    __syncthreads();

    int n = tid;
    float tn[64];
#pragma unroll
    for (int i = 0; i < 64; i++) tn[i] = g_t1[n * 64 + i] * g_sc3[i] + g_sh3[i];
    float acc = bo[0];
    for (int j = 0; j < 64; j++) {
        float s = bt2[j];
#pragma unroll
        for (int i = 0; i < 64; i++) s += tn[i] * W2[i * 64 + j];
        acc += fmaxf(s, 0.f) * wo[j];
    }
    out[n] = sigf(acc);
}

// ---------------------------------------------------------------------------
extern "C" void kernel_launch(void* const* d_in, const int* in_sizes, int n_in,
                              void* d_out, int out_size)
{
    const float* operators = (const float*)d_in[0];
    const float* extra     = (const float*)d_in[1];
    const float* card      = (const float*)d_in[2];
    const float* cond1     = (const float*)d_in[3];
    const float* cond2     = (const float*)d_in[4];
    const int*   mapping   = (const int*)  d_in[5];
    const float* Wih1      = (const float*)d_in[6];
    const float* Whh1      = (const float*)d_in[7];
    const float* b1        = (const float*)d_in[8];
    const float* Wc        = (const float*)d_in[9];
    const float* bc        = (const float*)d_in[10];
    const float* g1        = (const float*)d_in[11];
    const float* be1       = (const float*)d_in[12];
    const float* Wih2      = (const float*)d_in[13];
    // d_in[14] = Whh2: unused (single step from zero state)
    const float* b2        = (const float*)d_in[15];
    const float* Win       = (const float*)d_in[16];
    const float* bin_      = (const float*)d_in[17];
    const float* Wlh       = (const float*)d_in[18];
    const float* blh       = (const float*)d_in[19];
    const float* Wrh       = (const float*)d_in[20];
    const float* brh       = (const float*)d_in[21];
    const float* g2        = (const float*)d_in[22];
    const float* be2       = (const float*)d_in[23];
    const float* Wt1       = (const float*)d_in[24];
    const float* bt1       = (const float*)d_in[25];
    const float* g3        = (const float*)d_in[26];
    const float* be3       = (const float*)d_in[27];
    const float* Wt2       = (const float*)d_in[28];
    const float* bt2       = (const float*)d_in[29];
    const float* Wo        = (const float*)d_in[30];
    const float* bo        = (const float*)d_in[31];
    float* out = (float*)d_out;

    lstm1_kernel<<<128, 256>>>(cond1, cond2, Wih1, Whh1, b1);
    wcat_kernel<<<160, 1024>>>(Wlh, Wrh);
    lo_kernel<<<128, 256>>>(Wc, bc);
    bn_stats_kernel<<<1, 256>>>(0, g1, be1);
    lstm2_kernel<<<128, 128>>>(operators, extra, card, Wih2, b2);
    base_kernel<<<15, 128>>>(operators, extra, card, Win, bin_);

    for (int s = 0; s < 15; s++) {
        tree_gemm_kernel<<<dim3(8, 5), 128>>>(mapping, s);
        tree_pw_kernel<<<128, 128>>>(mapping, blh, brh, s);
    }

    bn_stats_kernel<<<1, 256>>>(1, g2, be2);
    t1_kernel<<<128, 64>>>(Wt1, bt1);
    bn_stats_kernel<<<1, 256>>>(2, g3, be3);
    final_kernel<<<1, 128>>>(Wt2, bt2, Wo, bo, out);
}